// round 6
// baseline (speedup 1.0000x reference)
#include <cuda_runtime.h>
#include <cuda_bf16.h>
#include <cstdint>

#define TT    2048
#define DM    2560
#define NH    8
#define NKV   4
#define HDIM  256
#define SEQL  8192
#define PREVL 4096
#define ATT_SCALE 0.0625f

// Scratch (device globals; no runtime allocation allowed)
__device__ float g_q[TT * NH * HDIM];     // [t][h][d]  (post rmsnorm+rope, *SCALE)
__device__ float g_k[TT * NKV * HDIM];    // [t][kv][d] (post rmsnorm+rope)
__device__ float g_v[TT * NKV * HDIM];    // [t][kv][d]
__device__ float g_ctx[TT * NH * HDIM];   // [t][h][d]

__device__ __forceinline__ uint32_t f2tf(float x) {
    uint32_t r;
    asm("cvt.rna.tf32.f32 %0, %1;" : "=r"(r) : "f"(x));
    return r;
}

__device__ __forceinline__ void mma8(float& c0, float& c1, float& c2, float& c3,
                                     uint32_t a0, uint32_t a1, uint32_t a2, uint32_t a3,
                                     uint32_t b0, uint32_t b1) {
    asm volatile(
        "mma.sync.aligned.m16n8k8.row.col.f32.tf32.tf32.f32 "
        "{%0,%1,%2,%3},{%4,%5,%6,%7},{%8,%9},{%0,%1,%2,%3};\n"
        : "+f"(c0), "+f"(c1), "+f"(c2), "+f"(c3)
        : "r"(a0), "r"(a1), "r"(a2), "r"(a3), "r"(b0), "r"(b1));
}

// ---------------------------------------------------------------------------
// tf32 GEMM:  C[M,N] = A[M,K] * B[N,K]^T   (row-major fp32 in/out)
// 128x128 tile, ktile=16, 8 warps (4x2), warp tile 32x64. Double buffered.
// M%128==0, N%128==0, K%16==0.
// ---------------------------------------------------------------------------
#define GST 20   // smem k-stride (16 + 4 pad)
__global__ void __launch_bounds__(256, 2) gemm_tf32(const float* __restrict__ A,
                                                    const float* __restrict__ B,
                                                    float* __restrict__ C,
                                                    int M, int N, int K) {
    __shared__ uint32_t As[2][128 * GST];
    __shared__ uint32_t Bs[2][128 * GST];

    const int tid = threadIdx.x;
    const int lane = tid & 31;
    const int warp = tid >> 5;
    const int wy = warp >> 1;          // 0..3 -> m offset 32*wy
    const int wx = warp & 1;           // 0..1 -> n offset 64*wx
    const int bm = blockIdx.y * 128;
    const int bn = blockIdx.x * 128;

    const int lr = tid >> 2;           // 0..63 loader row (pass adds 64)
    const int lc = (tid & 3) * 4;      // float4 col within ktile

    const float* Ap = A + (size_t)(bm + lr) * K + lc;
    const float* Bp = B + (size_t)(bn + lr) * K + lc;
    const size_t rowskip = (size_t)64 * K;

    float acc[2][8][4];
#pragma unroll
    for (int i = 0; i < 2; i++)
#pragma unroll
        for (int j = 0; j < 8; j++)
#pragma unroll
            for (int e = 0; e < 4; e++) acc[i][j][e] = 0.f;

    const int nk = K >> 4;

    // preload tile 0
    {
        float4 a0 = *(const float4*)Ap;
        float4 a1 = *(const float4*)(Ap + rowskip);
        float4 b0 = *(const float4*)Bp;
        float4 b1 = *(const float4*)(Bp + rowskip);
        uint32_t* as0 = &As[0][lr * GST + lc];
        uint32_t* as1 = &As[0][(lr + 64) * GST + lc];
        uint32_t* bs0 = &Bs[0][lr * GST + lc];
        uint32_t* bs1 = &Bs[0][(lr + 64) * GST + lc];
        as0[0] = f2tf(a0.x); as0[1] = f2tf(a0.y); as0[2] = f2tf(a0.z); as0[3] = f2tf(a0.w);
        as1[0] = f2tf(a1.x); as1[1] = f2tf(a1.y); as1[2] = f2tf(a1.z); as1[3] = f2tf(a1.w);
        bs0[0] = f2tf(b0.x); bs0[1] = f2tf(b0.y); bs0[2] = f2tf(b0.z); bs0[3] = f2tf(b0.w);
        bs1[0] = f2tf(b1.x); bs1[1] = f2tf(b1.y); bs1[2] = f2tf(b1.z); bs1[3] = f2tf(b1.w);
    }
    __syncthreads();

    int buf = 0;
    for (int kt = 0; kt < nk; kt++) {
        float4 pa0, pa1, pb0, pb1;
        const bool more = (kt + 1 < nk);
        if (more) {
            const float* ap = Ap + (kt + 1) * 16;
            const float* bp = Bp + (kt + 1) * 16;
            pa0 = *(const float4*)ap;
            pa1 = *(const float4*)(ap + rowskip);
            pb0 = *(const float4*)bp;
            pb1 = *(const float4*)(bp + rowskip);
        }

        const uint32_t* as = As[buf];
        const uint32_t* bs = Bs[buf];
#pragma unroll
        for (int c = 0; c < 2; c++) {
            const int kk = 8 * c;
            uint32_t af[2][4];
#pragma unroll
            for (int mt = 0; mt < 2; mt++) {
                int m = wy * 32 + mt * 16 + (lane >> 2);
                af[mt][0] = as[m * GST + kk + (lane & 3)];
                af[mt][1] = as[(m + 8) * GST + kk + (lane & 3)];
                af[mt][2] = as[m * GST + kk + (lane & 3) + 4];
                af[mt][3] = as[(m + 8) * GST + kk + (lane & 3) + 4];
            }
            uint32_t bf[8][2];
#pragma unroll
            for (int nt = 0; nt < 8; nt++) {
                int n = wx * 64 + nt * 8 + (lane >> 2);
                bf[nt][0] = bs[n * GST + kk + (lane & 3)];
                bf[nt][1] = bs[n * GST + kk + (lane & 3) + 4];
            }
#pragma unroll
            for (int mt = 0; mt < 2; mt++)
#pragma unroll
                for (int nt = 0; nt < 8; nt++)
                    mma8(acc[mt][nt][0], acc[mt][nt][1], acc[mt][nt][2], acc[mt][nt][3],
                         af[mt][0], af[mt][1], af[mt][2], af[mt][3],
                         bf[nt][0], bf[nt][1]);
        }

        if (more) {
            uint32_t* as0 = &As[buf ^ 1][lr * GST + lc];
            uint32_t* as1 = &As[buf ^ 1][(lr + 64) * GST + lc];
            uint32_t* bs0 = &Bs[buf ^ 1][lr * GST + lc];
            uint32_t* bs1 = &Bs[buf ^ 1][(lr + 64) * GST + lc];
            as0[0] = f2tf(pa0.x); as0[1] = f2tf(pa0.y); as0[2] = f2tf(pa0.z); as0[3] = f2tf(pa0.w);
            as1[0] = f2tf(pa1.x); as1[1] = f2tf(pa1.y); as1[2] = f2tf(pa1.z); as1[3] = f2tf(pa1.w);
            bs0[0] = f2tf(pb0.x); bs0[1] = f2tf(pb0.y); bs0[2] = f2tf(pb0.z); bs0[3] = f2tf(pb0.w);
            bs1[0] = f2tf(pb1.x); bs1[1] = f2tf(pb1.y); bs1[2] = f2tf(pb1.z); bs1[3] = f2tf(pb1.w);
        }
        __syncthreads();
        buf ^= 1;
    }

    // epilogue
#pragma unroll
    for (int mt = 0; mt < 2; mt++) {
        int row = bm + wy * 32 + mt * 16 + (lane >> 2);
#pragma unroll
        for (int nt = 0; nt < 8; nt++) {
            int col = bn + wx * 64 + nt * 8 + 2 * (lane & 3);
            *(float2*)&C[(size_t)row * N + col] = make_float2(acc[mt][nt][0], acc[mt][nt][1]);
            *(float2*)&C[(size_t)(row + 8) * N + col] = make_float2(acc[mt][nt][2], acc[mt][nt][3]);
        }
    }
}

// ---------------------------------------------------------------------------
// RMSNorm + RoPE (+SCALE for q), in place on g_q / g_k.
// ---------------------------------------------------------------------------
__global__ void __launch_bounds__(HDIM) rms_rope_kernel(const float* __restrict__ q_scale,
                                                        const float* __restrict__ k_scale,
                                                        const float* __restrict__ cosb,
                                                        const float* __restrict__ sinb) {
    const int t = blockIdx.x;
    const int hy = blockIdx.y;
    const int d = threadIdx.x;

    float* buf;
    const float* sc;
    bool isq;
    if (hy < NH) { buf = &g_q[((size_t)t * NH + hy) * HDIM]; sc = q_scale; isq = true; }
    else         { buf = &g_k[((size_t)t * NKV + (hy - NH)) * HDIM]; sc = k_scale; isq = false; }

    float xv = buf[d];
    int dp = (d < 128) ? d + 128 : d - 128;
    float xp = buf[dp];

    __shared__ float red[8];
    float s = xv * xv;
#pragma unroll
    for (int m = 16; m; m >>= 1) s += __shfl_xor_sync(0xffffffffu, s, m);
    if ((d & 31) == 0) red[d >> 5] = s;
    __syncthreads();
    if (d == 0) {
        float v = 0.f;
#pragma unroll
        for (int i = 0; i < 8; i++) v += red[i];
        red[0] = v;
    }
    __syncthreads();
    float inv = rsqrtf(red[0] * (1.0f / HDIM) + 1e-6f);

    float xn  = xv * inv * (1.f + sc[d]);
    float xpn = xp * inv * (1.f + sc[dp]);
    float rot = (d < 128) ? -xpn : xpn;
    float out = xn * cosb[t * HDIM + d] + rot * sinb[t * HDIM + d];
    if (isq) out *= ATT_SCALE;
    buf[d] = out;
}

// ---------------------------------------------------------------------------
// Flash attention, tf32 tensor cores.
// grid (32, 8), 256 threads = 8 warps: 4 row-groups (16 q rows) x 2 dim-halves.
// 64 queries x 64-key blocks. Q fragments register-resident.
// ---------------------------------------------------------------------------
#define KST 260   // K/V smem row stride (256 + 4)
#define SST 68    // score smem row stride (64 + 4)
__global__ void __launch_bounds__(256, 1) attn_kernel(const float* __restrict__ kcache,
                                                      const float* __restrict__ vcache) {
    extern __shared__ char smraw[];
    uint32_t* Ks = (uint32_t*)smraw;                 // [64][KST]
    uint32_t* Vs = Ks + 64 * KST;                    // [64][KST]
    float*    SPf = (float*)(Vs + 64 * KST);         // [64][SST]
    uint32_t* SPu = (uint32_t*)SPf;

    const int tid  = threadIdx.x;
    const int lane = tid & 31;
    const int warp = tid >> 5;
    const int rg   = warp >> 1;         // row group 0..3
    const int half = warp & 1;          // dim half 0..1
    const int m0   = rg * 16;
    const int d0   = half * 128;
    const int lq   = lane >> 2;         // 0..7
    const int lk   = lane & 3;          // 0..3

    const int qt = 31 - blockIdx.x;
    const int h  = blockIdx.y;
    const int kvh = h >> 1;
    const int t0 = qt * 64;

    // Q fragments: 16 k-chunks over this warp's 128 dims
    uint32_t qf[16][4];
    {
        const float* qb = g_q + (((size_t)(t0 + m0 + lq)) * NH + h) * HDIM + d0;
        const float* qb8 = qb + (size_t)8 * NH * HDIM;
#pragma unroll
        for (int c = 0; c < 16; c++) {
            qf[c][0] = f2tf(qb[8 * c + lk]);
            qf[c][1] = f2tf(qb8[8 * c + lk]);
            qf[c][2] = f2tf(qb[8 * c + lk + 4]);
            qf[c][3] = f2tf(qb8[8 * c + lk + 4]);
        }
    }

    float acc[16][4];
#pragma unroll
    for (int nt = 0; nt < 16; nt++)
#pragma unroll
        for (int e = 0; e < 4; e++) acc[nt][e] = 0.f;
    float mrow[2] = {-1e30f, -1e30f};
    float lrow[2] = {0.f, 0.f};

    const int nb = PREVL / 64 + qt + 1;
    for (int b = 0; b < nb; b++) {
        const int s0 = b * 64;
        const float* kbase;
        const float* vbase;
        if (s0 < PREVL) {
            kbase = kcache + ((size_t)s0 * NKV + kvh) * HDIM;
            vbase = vcache + ((size_t)s0 * NKV + kvh) * HDIM;
        } else {
            kbase = g_k + ((size_t)(s0 - PREVL) * NKV + kvh) * HDIM;
            vbase = g_v + ((size_t)(s0 - PREVL) * NKV + kvh) * HDIM;
        }
        // load K/V tiles (cvt to tf32)
        for (int idx = tid; idx < 64 * 64; idx += 256) {
            int r = idx >> 6, c4 = (idx & 63) * 4;
            float4 kv4 = *(const float4*)&kbase[(size_t)r * (NKV * HDIM) + c4];
            float4 vv4 = *(const float4*)&vbase[(size_t)r * (NKV * HDIM) + c4];
            uint32_t* kd = &Ks[r * KST + c4];
            uint32_t* vd = &Vs[r * KST + c4];
            kd[0] = f2tf(kv4.x); kd[1] = f2tf(kv4.y); kd[2] = f2tf(kv4.z); kd[3] = f2tf(kv4.w);
            vd[0] = f2tf(vv4.x); vd[1] = f2tf(vv4.y); vd[2] = f2tf(vv4.z); vd[3] = f2tf(vv4.w);
        }
        __syncthreads();

        // S_partial = Q_half * K_half^T : 8 n-tiles over 64 keys
        float sf[8][4];
#pragma unroll
        for (int nt = 0; nt < 8; nt++)
#pragma unroll
            for (int e = 0; e < 4; e++) sf[nt][e] = 0.f;
#pragma unroll
        for (int c = 0; c < 16; c++) {
            const int dd = d0 + 8 * c;
#pragma unroll
            for (int nt = 0; nt < 8; nt++) {
                uint32_t b0 = Ks[(nt * 8 + lq) * KST + dd + lk];
                uint32_t b1 = Ks[(nt * 8 + lq) * KST + dd + lk + 4];
                mma8(sf[nt][0], sf[nt][1], sf[nt][2], sf[nt][3],
                     qf[c][0], qf[c][1], qf[c][2], qf[c][3], b0, b1);
            }
        }

        // reduce the two halves through smem
        if (half == 0) {
#pragma unroll
            for (int nt = 0; nt < 8; nt++) {
                int col = nt * 8 + 2 * lk;
                SPf[(m0 + lq) * SST + col]     = sf[nt][0];
                SPf[(m0 + lq) * SST + col + 1] = sf[nt][1];
                SPf[(m0 + lq + 8) * SST + col]     = sf[nt][2];
                SPf[(m0 + lq + 8) * SST + col + 1] = sf[nt][3];
            }
        }
        __syncthreads();
        if (half == 1) {
#pragma unroll
            for (int nt = 0; nt < 8; nt++) {
                int col = nt * 8 + 2 * lk;
                SPf[(m0 + lq) * SST + col]     += sf[nt][0];
                SPf[(m0 + lq) * SST + col + 1] += sf[nt][1];
                SPf[(m0 + lq + 8) * SST + col]     += sf[nt][2];
                SPf[(m0 + lq + 8) * SST + col + 1] += sf[nt][3];
            }
        }
        __syncthreads();

        // read back summed scores (both halves, redundant)
#pragma unroll
        for (int nt = 0; nt < 8; nt++) {
            int col = nt * 8 + 2 * lk;
            sf[nt][0] = SPf[(m0 + lq) * SST + col];
            sf[nt][1] = SPf[(m0 + lq) * SST + col + 1];
            sf[nt][2] = SPf[(m0 + lq + 8) * SST + col];
            sf[nt][3] = SPf[(m0 + lq + 8) * SST + col + 1];
        }
        const bool diag = (b == nb - 1);
        if (diag) {
            // causal mask within diagonal block: key index (col) vs query
            // index within the 64-row tile. Query rows are m0+lq and m0+lq+8.
            const int qr0 = m0 + lq;
            const int qr1 = m0 + lq + 8;
#pragma unroll
            for (int nt = 0; nt < 8; nt++) {
                int col = nt * 8 + 2 * lk;
                if (col > qr0)          sf[nt][0] = -1e30f;
                if (col + 1 > qr0)      sf[nt][1] = -1e30f;
                if (col > qr1)          sf[nt][2] = -1e30f;
                if (col + 1 > qr1)      sf[nt][3] = -1e30f;
            }
        }

        // online softmax per row j (rows lq and lq+8 within row group)
#pragma unroll
        for (int j = 0; j < 2; j++) {
            float rmax = -1e30f;
#pragma unroll
            for (int nt = 0; nt < 8; nt++) {
                rmax = fmaxf(rmax, sf[nt][2 * j]);
                rmax = fmaxf(rmax, sf[nt][2 * j + 1]);
            }
            rmax = fmaxf(rmax, __shfl_xor_sync(0xffffffffu, rmax, 1));
            rmax = fmaxf(rmax, __shfl_xor_sync(0xffffffffu, rmax, 2));
            float mnew = fmaxf(mrow[j], rmax);
            float resc = __expf(mrow[j] - mnew);
            mrow[j] = mnew;
            float rs = 0.f;
#pragma unroll
            for (int nt = 0; nt < 8; nt++) {
                float p0 = __expf(sf[nt][2 * j] - mnew);
                float p1 = __expf(sf[nt][2 * j + 1] - mnew);
                sf[nt][2 * j] = p0;
                sf[nt][2 * j + 1] = p1;
                rs += p0 + p1;
            }
            rs += __shfl_xor_sync(0xffffffffu, rs, 1);
            rs += __shfl_xor_sync(0xffffffffu, rs, 2);
            lrow[j] = lrow[j] * resc + rs;
#pragma unroll
            for (int nt = 0; nt < 16; nt++) {
                acc[nt][2 * j] *= resc;
                acc[nt][2 * j + 1] *= resc;
            }
        }
        __syncthreads();  // all SP reads done before overwrite with P

        // write P (tf32) — half 0 only (identical values in both halves)
        if (half == 0) {
#pragma unroll
            for (int nt = 0; nt < 8; nt++) {
                int col = nt * 8 + 2 * lk;
                SPu[(m0 + lq) * SST + col]     = f2tf(sf[nt][0]);
                SPu[(m0 + lq) * SST + col + 1] = f2tf(sf[nt][1]);
                SPu[(m0 + lq + 8) * SST + col]     = f2tf(sf[nt][2]);
                SPu[(m0 + lq + 8) * SST + col + 1] = f2tf(sf[nt][3]);
            }
        }
        __syncthreads();

        // ctx_half += P * V_half : 8 k-chunks x 16 n-tiles
#pragma unroll
        for (int kc = 0; kc < 8; kc++) {
            uint32_t a0 = SPu[(m0 + lq) * SST + kc * 8 + lk];
            uint32_t a1 = SPu[(m0 + lq + 8) * SST + kc * 8 + lk];
            uint32_t a2 = SPu[(m0 + lq) * SST + kc * 8 + lk + 4];
            uint32_t a3 = SPu[(m0 + lq + 8) * SST + kc * 8 + lk + 4];
#pragma unroll
            for (int nt = 0; nt < 16; nt++) {
                int d = d0 + nt * 8 + lq;
                uint32_t b0 = Vs[(kc * 8 + lk) * KST + d];
                uint32_t b1 = Vs[(kc * 8 + lk + 4) * KST + d];
                mma8(acc[nt][0], acc[nt][1], acc[nt][2], acc[nt][3],
                     a0, a1, a2, a3, b0, b1);
            }
        }
        __syncthreads();  // before next block overwrites Ks/Vs/SP
    }

    // epilogue
    float linv0 = 1.f / lrow[0];
    float linv1 = 1.f / lrow[1];
    {
        size_t row0 = (size_t)(t0 + m0 + lq) * (NH * HDIM) + (size_t)h * HDIM;
        size_t row1 = row0 + (size_t)8 * NH * HDIM;
#pragma unroll
        for (int nt = 0; nt < 16; nt++) {
            int col = d0 + nt * 8 + 2 * lk;
            *(float2*)&g_ctx[row0 + col] = make_float2(acc[nt][0] * linv0, acc[nt][1] * linv0);
            *(float2*)&g_ctx[row1 + col] = make_float2(acc[nt][2] * linv1, acc[nt][3] * linv1);
        }
    }
}

// ---------------------------------------------------------------------------
extern "C" void kernel_launch(void* const* d_in, const int* in_sizes, int n_in,
                              void* d_out, int out_size) {
    const float* x   = (const float*)d_in[0];
    const float* Wq  = (const float*)d_in[1];
    const float* Wk  = (const float*)d_in[2];
    const float* Wv  = (const float*)d_in[3];
    const float* Wo  = (const float*)d_in[4];
    const float* qsc = (const float*)d_in[5];
    const float* ksc = (const float*)d_in[6];
    const float* kc  = (const float*)d_in[7];
    const float* vc  = (const float*)d_in[8];
    const float* cs  = (const float*)d_in[9];
    const float* sn  = (const float*)d_in[10];
    float* out = (float*)d_out;

    float *q, *k, *v, *ctx;
    cudaGetSymbolAddress((void**)&q,   g_q);
    cudaGetSymbolAddress((void**)&k,   g_k);
    cudaGetSymbolAddress((void**)&v,   g_v);
    cudaGetSymbolAddress((void**)&ctx, g_ctx);

    // QKV projections (tf32 tensor cores)
    gemm_tf32<<<dim3(16, 16), 256>>>(x, Wq, q, TT, NH * HDIM, DM);
    gemm_tf32<<<dim3(8, 16), 256>>>(x, Wk, k, TT, NKV * HDIM, DM);
    gemm_tf32<<<dim3(8, 16), 256>>>(x, Wv, v, TT, NKV * HDIM, DM);

    // RMSNorm + RoPE (+SCALE on q)
    rms_rope_kernel<<<dim3(TT, NH + NKV), HDIM>>>(qsc, ksc, cs, sn);

    // Attention (tf32 tensor cores)
    size_t smem = (size_t)(2 * 64 * KST + 64 * SST) * sizeof(float);
    cudaFuncSetAttribute(attn_kernel, cudaFuncAttributeMaxDynamicSharedMemorySize, (int)smem);
    attn_kernel<<<dim3(32, NH), 256, smem>>>(kc, vc);

    // Output projection
    gemm_tf32<<<dim3(20, 16), 256>>>(ctx, Wo, out, TT, DM, NH * HDIM);
}

// round 7
// speedup vs baseline: 1.0873x; 1.0873x over previous
#include <cuda_runtime.h>
#include <cuda_bf16.h>
#include <cstdint>

#define TT    2048
#define DM    2560
#define NH    8
#define NKV   4
#define HDIM  256
#define SEQL  8192
#define PREVL 4096
#define ATT_SCALE 0.0625f

// Scratch (device globals; no runtime allocation allowed)
__device__ float g_q[TT * NH * HDIM];        // [t][h][d]  (post rmsnorm+rope, *SCALE, tf32-rounded)
__device__ float g_k[TT * NKV * HDIM];       // [t][kv][d] (post rmsnorm+rope, tf32-rounded)
__device__ float g_v[TT * NKV * HDIM];       // [t][kv][d] (tf32-rounded by prep)
__device__ float g_ctx[TT * NH * HDIM];      // [t][h][d]  (fp32)
__device__ float g_kc[PREVL * NKV * HDIM];   // tf32-rounded copy of k_cache[0:PREVL]
__device__ float g_vc[PREVL * NKV * HDIM];   // tf32-rounded copy of v_cache[0:PREVL]

__device__ __forceinline__ uint32_t f2tf(float x) {
    uint32_t r;
    asm("cvt.rna.tf32.f32 %0, %1;" : "=r"(r) : "f"(x));
    return r;
}

__device__ __forceinline__ void mma8(float& c0, float& c1, float& c2, float& c3,
                                     uint32_t a0, uint32_t a1, uint32_t a2, uint32_t a3,
                                     uint32_t b0, uint32_t b1) {
    asm volatile(
        "mma.sync.aligned.m16n8k8.row.col.f32.tf32.tf32.f32 "
        "{%0,%1,%2,%3},{%4,%5,%6,%7},{%8,%9},{%0,%1,%2,%3};\n"
        : "+f"(c0), "+f"(c1), "+f"(c2), "+f"(c3)
        : "r"(a0), "r"(a1), "r"(a2), "r"(a3), "r"(b0), "r"(b1));
}

__device__ __forceinline__ void cpa16(uint32_t dst, const float* src) {
    asm volatile("cp.async.cg.shared.global [%0], [%1], 16;" :: "r"(dst), "l"(src));
}

// ---------------------------------------------------------------------------
// tf32 GEMM:  C[M,N] = A[M,K] * B[N,K]^T   (row-major fp32 in/out)  (unchanged)
// ---------------------------------------------------------------------------
#define GST 20
__global__ void __launch_bounds__(256, 2) gemm_tf32(const float* __restrict__ A,
                                                    const float* __restrict__ B,
                                                    float* __restrict__ C,
                                                    int M, int N, int K) {
    __shared__ uint32_t As[2][128 * GST];
    __shared__ uint32_t Bs[2][128 * GST];

    const int tid = threadIdx.x;
    const int lane = tid & 31;
    const int warp = tid >> 5;
    const int wy = warp >> 1;
    const int wx = warp & 1;
    const int bm = blockIdx.y * 128;
    const int bn = blockIdx.x * 128;

    const int lr = tid >> 2;
    const int lc = (tid & 3) * 4;

    const float* Ap = A + (size_t)(bm + lr) * K + lc;
    const float* Bp = B + (size_t)(bn + lr) * K + lc;
    const size_t rowskip = (size_t)64 * K;

    float acc[2][8][4];
#pragma unroll
    for (int i = 0; i < 2; i++)
#pragma unroll
        for (int j = 0; j < 8; j++)
#pragma unroll
            for (int e = 0; e < 4; e++) acc[i][j][e] = 0.f;

    const int nk = K >> 4;

    {
        float4 a0 = *(const float4*)Ap;
        float4 a1 = *(const float4*)(Ap + rowskip);
        float4 b0 = *(const float4*)Bp;
        float4 b1 = *(const float4*)(Bp + rowskip);
        uint32_t* as0 = &As[0][lr * GST + lc];
        uint32_t* as1 = &As[0][(lr + 64) * GST + lc];
        uint32_t* bs0 = &Bs[0][lr * GST + lc];
        uint32_t* bs1 = &Bs[0][(lr + 64) * GST + lc];
        as0[0] = f2tf(a0.x); as0[1] = f2tf(a0.y); as0[2] = f2tf(a0.z); as0[3] = f2tf(a0.w);
        as1[0] = f2tf(a1.x); as1[1] = f2tf(a1.y); as1[2] = f2tf(a1.z); as1[3] = f2tf(a1.w);
        bs0[0] = f2tf(b0.x); bs0[1] = f2tf(b0.y); bs0[2] = f2tf(b0.z); bs0[3] = f2tf(b0.w);
        bs1[0] = f2tf(b1.x); bs1[1] = f2tf(b1.y); bs1[2] = f2tf(b1.z); bs1[3] = f2tf(b1.w);
    }
    __syncthreads();

    int buf = 0;
    for (int kt = 0; kt < nk; kt++) {
        float4 pa0, pa1, pb0, pb1;
        const bool more = (kt + 1 < nk);
        if (more) {
            const float* ap = Ap + (kt + 1) * 16;
            const float* bp = Bp + (kt + 1) * 16;
            pa0 = *(const float4*)ap;
            pa1 = *(const float4*)(ap + rowskip);
            pb0 = *(const float4*)bp;
            pb1 = *(const float4*)(bp + rowskip);
        }

        const uint32_t* as = As[buf];
        const uint32_t* bs = Bs[buf];
#pragma unroll
        for (int c = 0; c < 2; c++) {
            const int kk = 8 * c;
            uint32_t af[2][4];
#pragma unroll
            for (int mt = 0; mt < 2; mt++) {
                int m = wy * 32 + mt * 16 + (lane >> 2);
                af[mt][0] = as[m * GST + kk + (lane & 3)];
                af[mt][1] = as[(m + 8) * GST + kk + (lane & 3)];
                af[mt][2] = as[m * GST + kk + (lane & 3) + 4];
                af[mt][3] = as[(m + 8) * GST + kk + (lane & 3) + 4];
            }
            uint32_t bf[8][2];
#pragma unroll
            for (int nt = 0; nt < 8; nt++) {
                int n = wx * 64 + nt * 8 + (lane >> 2);
                bf[nt][0] = bs[n * GST + kk + (lane & 3)];
                bf[nt][1] = bs[n * GST + kk + (lane & 3) + 4];
            }
#pragma unroll
            for (int mt = 0; mt < 2; mt++)
#pragma unroll
                for (int nt = 0; nt < 8; nt++)
                    mma8(acc[mt][nt][0], acc[mt][nt][1], acc[mt][nt][2], acc[mt][nt][3],
                         af[mt][0], af[mt][1], af[mt][2], af[mt][3],
                         bf[nt][0], bf[nt][1]);
        }

        if (more) {
            uint32_t* as0 = &As[buf ^ 1][lr * GST + lc];
            uint32_t* as1 = &As[buf ^ 1][(lr + 64) * GST + lc];
            uint32_t* bs0 = &Bs[buf ^ 1][lr * GST + lc];
            uint32_t* bs1 = &Bs[buf ^ 1][(lr + 64) * GST + lc];
            as0[0] = f2tf(pa0.x); as0[1] = f2tf(pa0.y); as0[2] = f2tf(pa0.z); as0[3] = f2tf(pa0.w);
            as1[0] = f2tf(pa1.x); as1[1] = f2tf(pa1.y); as1[2] = f2tf(pa1.z); as1[3] = f2tf(pa1.w);
            bs0[0] = f2tf(pb0.x); bs0[1] = f2tf(pb0.y); bs0[2] = f2tf(pb0.z); bs0[3] = f2tf(pb0.w);
            bs1[0] = f2tf(pb1.x); bs1[1] = f2tf(pb1.y); bs1[2] = f2tf(pb1.z); bs1[3] = f2tf(pb1.w);
        }
        __syncthreads();
        buf ^= 1;
    }

#pragma unroll
    for (int mt = 0; mt < 2; mt++) {
        int row = bm + wy * 32 + mt * 16 + (lane >> 2);
#pragma unroll
        for (int nt = 0; nt < 8; nt++) {
            int col = bn + wx * 64 + nt * 8 + 2 * (lane & 3);
            *(float2*)&C[(size_t)row * N + col] = make_float2(acc[mt][nt][0], acc[mt][nt][1]);
            *(float2*)&C[(size_t)(row + 8) * N + col] = make_float2(acc[mt][nt][2], acc[mt][nt][3]);
        }
    }
}

// ---------------------------------------------------------------------------
// Prep: tf32-round k_cache/v_cache (used half) into g_kc/g_vc; round g_v in place.
// ---------------------------------------------------------------------------
__global__ void __launch_bounds__(256) prep_kernel(const float* __restrict__ kc,
                                                   const float* __restrict__ vc) {
    const int n1 = PREVL * NKV * HDIM / 4;
    const int n2 = n1;
    const int n3 = TT * NKV * HDIM / 4;
    const int total = n1 + n2 + n3;
    for (int i = blockIdx.x * blockDim.x + threadIdx.x; i < total;
         i += gridDim.x * blockDim.x) {
        float4 v;
        float4* dst;
        if (i < n1)           { v = ((const float4*)kc)[i];      dst = &((float4*)g_kc)[i]; }
        else if (i < n1 + n2) { v = ((const float4*)vc)[i - n1]; dst = &((float4*)g_vc)[i - n1]; }
        else { int j = i - n1 - n2; v = ((float4*)g_v)[j];       dst = &((float4*)g_v)[j]; }
        v.x = __uint_as_float(f2tf(v.x));
        v.y = __uint_as_float(f2tf(v.y));
        v.z = __uint_as_float(f2tf(v.z));
        v.w = __uint_as_float(f2tf(v.w));
        *dst = v;
    }
}

// ---------------------------------------------------------------------------
// RMSNorm + RoPE (+SCALE for q), in place; outputs tf32-rounded.
// ---------------------------------------------------------------------------
__global__ void __launch_bounds__(HDIM) rms_rope_kernel(const float* __restrict__ q_scale,
                                                        const float* __restrict__ k_scale,
                                                        const float* __restrict__ cosb,
                                                        const float* __restrict__ sinb) {
    const int t = blockIdx.x;
    const int hy = blockIdx.y;
    const int d = threadIdx.x;

    float* buf;
    const float* sc;
    bool isq;
    if (hy < NH) { buf = &g_q[((size_t)t * NH + hy) * HDIM]; sc = q_scale; isq = true; }
    else         { buf = &g_k[((size_t)t * NKV + (hy - NH)) * HDIM]; sc = k_scale; isq = false; }

    float xv = buf[d];
    int dp = (d < 128) ? d + 128 : d - 128;
    float xp = buf[dp];

    __shared__ float red[8];
    float s = xv * xv;
#pragma unroll
    for (int m = 16; m; m >>= 1) s += __shfl_xor_sync(0xffffffffu, s, m);
    if ((d & 31) == 0) red[d >> 5] = s;
    __syncthreads();
    if (d == 0) {
        float v = 0.f;
#pragma unroll
        for (int i = 0; i < 8; i++) v += red[i];
        red[0] = v;
    }
    __syncthreads();
    float inv = rsqrtf(red[0] * (1.0f / HDIM) + 1e-6f);

    float xn  = xv * inv * (1.f + sc[d]);
    float xpn = xp * inv * (1.f + sc[dp]);
    float rot = (d < 128) ? -xpn : xpn;
    float out = xn * cosb[t * HDIM + d] + rot * sinb[t * HDIM + d];
    if (isq) out *= ATT_SCALE;
    buf[d] = __uint_as_float(f2tf(out));   // pre-round: attention reads raw bits
}

// ---------------------------------------------------------------------------
// Flash attention, tf32 tensor cores, cp.async double-buffered 32-key blocks.
// grid (32, 8), 256 threads = 8 warps: 4 row-groups (16 q rows) x 2 dim-halves.
// All operands pre-rounded to tf32 in gmem -> raw cp.async, no cvt in kernel.
// ---------------------------------------------------------------------------
#define KST2 260   // K/V smem row stride (256 + 4); 260 % 32 == 4
#define SPW  36    // score/P smem row stride (32 + 4); 36 % 32 == 4
__global__ void __launch_bounds__(256, 1) attn_kernel(const float* __restrict__ kcache_unused,
                                                      const float* __restrict__ vcache_unused) {
    extern __shared__ __align__(16) float sm[];
    float* Ks  = sm;                       // [2][32][KST2]
    float* Vs  = Ks + 2 * 32 * KST2;       // [2][32][KST2]
    float* SPf = Vs + 2 * 32 * KST2;       // [64][SPW]
    uint32_t* SPu = (uint32_t*)SPf;
    const uint32_t ks_u32 = (uint32_t)__cvta_generic_to_shared(Ks);
    const uint32_t vs_u32 = (uint32_t)__cvta_generic_to_shared(Vs);

    const int tid  = threadIdx.x;
    const int lane = tid & 31;
    const int warp = tid >> 5;
    const int rg   = warp >> 1;
    const int half = warp & 1;
    const int m0   = rg * 16;
    const int d0   = half * 128;
    const int lq   = lane >> 2;
    const int lk   = lane & 3;

    const int qt = 31 - blockIdx.x;        // heavy tiles first
    const int h  = blockIdx.y;
    const int kvh = h >> 1;
    const int t0 = qt * 64;
    const int nb = 130 + 2 * qt;           // 32-key blocks covering [0, PREVL+t0+64)

    // Q fragments (pre-rounded tf32 bits; 16 k8-chunks over this warp's 128 dims)
    uint32_t qf[16][4];
    {
        const float* qb  = g_q + (((size_t)(t0 + m0 + lq)) * NH + h) * HDIM + d0;
        const float* qb8 = qb + (size_t)8 * NH * HDIM;
#pragma unroll
        for (int c = 0; c < 16; c++) {
            qf[c][0] = __float_as_uint(qb[8 * c + lk]);
            qf[c][1] = __float_as_uint(qb8[8 * c + lk]);
            qf[c][2] = __float_as_uint(qb[8 * c + lk + 4]);
            qf[c][3] = __float_as_uint(qb8[8 * c + lk + 4]);
        }
    }

    float acc[16][4];
#pragma unroll
    for (int nt = 0; nt < 16; nt++)
#pragma unroll
        for (int e = 0; e < 4; e++) acc[nt][e] = 0.f;
    float mrow[2] = {-1e30f, -1e30f};
    float lrow[2] = {0.f, 0.f};

    // ---- cp.async issue of one 32-key block into buffer bf ----
    auto issue = [&](int b, int bf) {
        const int s0 = b * 32;
        const float* kb;
        const float* vb;
        if (s0 < PREVL) {
            kb = g_kc + ((size_t)s0 * NKV + kvh) * HDIM;
            vb = g_vc + ((size_t)s0 * NKV + kvh) * HDIM;
        } else {
            kb = g_k + ((size_t)(s0 - PREVL) * NKV + kvh) * HDIM;
            vb = g_v + ((size_t)(s0 - PREVL) * NKV + kvh) * HDIM;
        }
        const uint32_t kdst = ks_u32 + (uint32_t)(bf * 32 * KST2) * 4;
        const uint32_t vdst = vs_u32 + (uint32_t)(bf * 32 * KST2) * 4;
#pragma unroll
        for (int i = 0; i < 8; i++) {
            int idx = tid + i * 256;        // 0..2047
            int r  = idx >> 6;              // key row 0..31
            int c4 = (idx & 63) * 4;        // dim
            cpa16(kdst + (uint32_t)(r * KST2 + c4) * 4, kb + (size_t)r * (NKV * HDIM) + c4);
            cpa16(vdst + (uint32_t)(r * KST2 + c4) * 4, vb + (size_t)r * (NKV * HDIM) + c4);
        }
        asm volatile("cp.async.commit_group;");
    };

    issue(0, 0);
    int buf = 0;

    for (int b = 0; b < nb; b++) {
        if (b + 1 < nb) {
            issue(b + 1, buf ^ 1);
            asm volatile("cp.async.wait_group 1;");
        } else {
            asm volatile("cp.async.wait_group 0;");
        }
        __syncthreads();   // A: block b's K/V visible to all

        const float* ksb = Ks + buf * 32 * KST2;
        const float* vsb = Vs + buf * 32 * KST2;

        // S_partial = Q_half * K_half^T : 4 n-tiles over 32 keys
        float sf[4][4];
#pragma unroll
        for (int nt = 0; nt < 4; nt++)
#pragma unroll
            for (int e = 0; e < 4; e++) sf[nt][e] = 0.f;
#pragma unroll
        for (int c = 0; c < 16; c++) {
            const int dd = d0 + 8 * c;
#pragma unroll
            for (int nt = 0; nt < 4; nt++) {
                uint32_t b0 = __float_as_uint(ksb[(nt * 8 + lq) * KST2 + dd + lk]);
                uint32_t b1 = __float_as_uint(ksb[(nt * 8 + lq) * KST2 + dd + lk + 4]);
                mma8(sf[nt][0], sf[nt][1], sf[nt][2], sf[nt][3],
                     qf[c][0], qf[c][1], qf[c][2], qf[c][3], b0, b1);
            }
        }

        // reduce the two dim-halves through smem
        if (half == 0) {
#pragma unroll
            for (int nt = 0; nt < 4; nt++) {
                int col = nt * 8 + 2 * lk;
                SPf[(m0 + lq) * SPW + col]     = sf[nt][0];
                SPf[(m0 + lq) * SPW + col + 1] = sf[nt][1];
                SPf[(m0 + lq + 8) * SPW + col]     = sf[nt][2];
                SPf[(m0 + lq + 8) * SPW + col + 1] = sf[nt][3];
            }
        }
        __syncthreads();   // B
        if (half == 1) {
#pragma unroll
            for (int nt = 0; nt < 4; nt++) {
                int col = nt * 8 + 2 * lk;
                SPf[(m0 + lq) * SPW + col]     += sf[nt][0];
                SPf[(m0 + lq) * SPW + col + 1] += sf[nt][1];
                SPf[(m0 + lq + 8) * SPW + col]     += sf[nt][2];
                SPf[(m0 + lq + 8) * SPW + col + 1] += sf[nt][3];
            }
        }
        __syncthreads();   // C

        // read back summed scores
#pragma unroll
        for (int nt = 0; nt < 4; nt++) {
            int col = nt * 8 + 2 * lk;
            sf[nt][0] = SPf[(m0 + lq) * SPW + col];
            sf[nt][1] = SPf[(m0 + lq) * SPW + col + 1];
            sf[nt][2] = SPf[(m0 + lq + 8) * SPW + col];
            sf[nt][3] = SPf[(m0 + lq + 8) * SPW + col + 1];
        }

        // causal mask (active only for the last two blocks of this tile)
        const int rel = b * 32 - PREVL - t0;   // key rel index = rel + col
        if (rel > -32) {
            const int qr0 = m0 + lq;
            const int qr1 = m0 + lq + 8;
#pragma unroll
            for (int nt = 0; nt < 4; nt++) {
                int col = nt * 8 + 2 * lk;
                if (rel + col > qr0)     sf[nt][0] = -1e30f;
                if (rel + col + 1 > qr0) sf[nt][1] = -1e30f;
                if (rel + col > qr1)     sf[nt][2] = -1e30f;
                if (rel + col + 1 > qr1) sf[nt][3] = -1e30f;
            }
        }

        // online softmax (rows m0+lq and m0+lq+8)
#pragma unroll
        for (int j = 0; j < 2; j++) {
            float rmax = -1e30f;
#pragma unroll
            for (int nt = 0; nt < 4; nt++) {
                rmax = fmaxf(rmax, sf[nt][2 * j]);
                rmax = fmaxf(rmax, sf[nt][2 * j + 1]);
            }
            rmax = fmaxf(rmax, __shfl_xor_sync(0xffffffffu, rmax, 1));
            rmax = fmaxf(rmax, __shfl_xor_sync(0xffffffffu, rmax, 2));
            float mnew = fmaxf(mrow[j], rmax);
            float resc = __expf(mrow[j] - mnew);
            mrow[j] = mnew;
            float rs = 0.f;
#pragma unroll
            for (int nt = 0; nt < 4; nt++) {
                float p0 = __expf(sf[nt][2 * j] - mnew);
                float p1 = __expf(sf[nt][2 * j + 1] - mnew);
                sf[nt][2 * j] = p0;
                sf[nt][2 * j + 1] = p1;
                rs += p0 + p1;
            }
            rs += __shfl_xor_sync(0xffffffffu, rs, 1);
            rs += __shfl_xor_sync(0xffffffffu, rs, 2);
            lrow[j] = lrow[j] * resc + rs;
#pragma unroll
            for (int nt = 0; nt < 16; nt++) {
                acc[nt][2 * j] *= resc;
                acc[nt][2 * j + 1] *= resc;
            }
        }
        __syncthreads();   // D: all SPf reads done

        // write P (tf32) — half 0 only
        if (half == 0) {
#pragma unroll
            for (int nt = 0; nt < 4; nt++) {
                int col = nt * 8 + 2 * lk;
                SPu[(m0 + lq) * SPW + col]     = f2tf(sf[nt][0]);
                SPu[(m0 + lq) * SPW + col + 1] = f2tf(sf[nt][1]);
                SPu[(m0 + lq + 8) * SPW + col]     = f2tf(sf[nt][2]);
                SPu[(m0 + lq + 8) * SPW + col + 1] = f2tf(sf[nt][3]);
            }
        }
        __syncthreads();   // E

        // ctx_half += P * V_half : 4 k8-chunks x 16 n-tiles
#pragma unroll
        for (int kc2 = 0; kc2 < 4; kc2++) {
            uint32_t a0 = SPu[(m0 + lq) * SPW + kc2 * 8 + lk];
            uint32_t a1 = SPu[(m0 + lq + 8) * SPW + kc2 * 8 + lk];
            uint32_t a2 = SPu[(m0 + lq) * SPW + kc2 * 8 + lk + 4];
            uint32_t a3 = SPu[(m0 + lq + 8) * SPW + kc2 * 8 + lk + 4];
#pragma unroll
            for (int nt = 0; nt < 16; nt++) {
                int d = d0 + nt * 8 + lq;
                uint32_t b0 = __float_as_uint(vsb[(kc2 * 8 + lk) * KST2 + d]);
                uint32_t b1 = __float_as_uint(vsb[(kc2 * 8 + lk + 4) * KST2 + d]);
                mma8(acc[nt][0], acc[nt][1], acc[nt][2], acc[nt][3],
                     a0, a1, a2, a3, b0, b1);
            }
        }
        __syncthreads();   // F: buf free for reuse
        buf ^= 1;
    }

    // epilogue
    float linv0 = 1.f / lrow[0];
    float linv1 = 1.f / lrow[1];
    {
        size_t row0 = (size_t)(t0 + m0 + lq) * (NH * HDIM) + (size_t)h * HDIM;
        size_t row1 = row0 + (size_t)8 * NH * HDIM;
#pragma unroll
        for (int nt = 0; nt < 16; nt++) {
            int col = d0 + nt * 8 + 2 * lk;
            *(float2*)&g_ctx[row0 + col] = make_float2(acc[nt][0] * linv0, acc[nt][1] * linv0);
            *(float2*)&g_ctx[row1 + col] = make_float2(acc[nt][2] * linv1, acc[nt][3] * linv1);
        }
    }
}

// ---------------------------------------------------------------------------
extern "C" void kernel_launch(void* const* d_in, const int* in_sizes, int n_in,
                              void* d_out, int out_size) {
    const float* x   = (const float*)d_in[0];
    const float* Wq  = (const float*)d_in[1];
    const float* Wk  = (const float*)d_in[2];
    const float* Wv  = (const float*)d_in[3];
    const float* Wo  = (const float*)d_in[4];
    const float* qsc = (const float*)d_in[5];
    const float* ksc = (const float*)d_in[6];
    const float* kc  = (const float*)d_in[7];
    const float* vc  = (const float*)d_in[8];
    const float* cs  = (const float*)d_in[9];
    const float* sn  = (const float*)d_in[10];
    float* out = (float*)d_out;

    float *q, *k, *v, *ctx;
    cudaGetSymbolAddress((void**)&q,   g_q);
    cudaGetSymbolAddress((void**)&k,   g_k);
    cudaGetSymbolAddress((void**)&v,   g_v);
    cudaGetSymbolAddress((void**)&ctx, g_ctx);

    // QKV projections (tf32 tensor cores)
    gemm_tf32<<<dim3(16, 16), 256>>>(x, Wq, q, TT, NH * HDIM, DM);
    gemm_tf32<<<dim3(8, 16), 256>>>(x, Wk, k, TT, NKV * HDIM, DM);
    gemm_tf32<<<dim3(8, 16), 256>>>(x, Wv, v, TT, NKV * HDIM, DM);

    // Pre-round caches + g_v to tf32 (enables raw cp.async in attention)
    prep_kernel<<<1024, 256>>>(kc, vc);

    // RMSNorm + RoPE (+SCALE on q), outputs tf32-rounded
    rms_rope_kernel<<<dim3(TT, NH + NKV), HDIM>>>(qsc, ksc, cs, sn);

    // Attention (tf32, cp.async pipelined)
    size_t smem = (size_t)(4 * 32 * KST2 + 64 * SPW) * sizeof(float);
    cudaFuncSetAttribute(attn_kernel, cudaFuncAttributeMaxDynamicSharedMemorySize, (int)smem);
    attn_kernel<<<dim3(32, NH), 256, smem>>>(kc, vc);

    // Output projection
    gemm_tf32<<<dim3(20, 16), 256>>>(ctx, Wo, out, TT, DM, NH * HDIM);
}